// round 7
// baseline (speedup 1.0000x reference)
#include <cuda_runtime.h>
#include <cuda_bf16.h>

// ALiBi bias materialization:
//   out[z, i, j] = -slopes[z % 16] * |i - j|
//   z in [0, 64)  (h = z % 16), i, j in [0, 2048)
// Output: 64 * 2048 * 2048 fp32 = 1 GiB -> pure HBM-write-bound.
//
// R7: one block = one full row. 512 threads x float4 = 2048 floats; grid
// 131072. Same oversubscribed pattern as the 147.26us best (R1/R6) with
// half the CTA-dispatch traffic. Probing the last shape in the neutral
// family; if neutral, R6 kernel is final at the DRAM-write wall
// (~7.0 TB/s, 85.5% DRAM duty cycle).

#define S        2048
#define NUM_H    16
#define Z_TOTAL  64
#define THREADS  512                      // 512 * 4 floats = one row

__global__ __launch_bounds__(THREADS)
void alibi_kernel(const float* __restrict__ slopes, float* __restrict__ out) {
    const unsigned row = blockIdx.x;                  // [0, 131072)
    const unsigned i   = row & (S - 1);
    const unsigned h   = (row >> 11) & (NUM_H - 1);   // z % 16

    const float neg_slope = -__ldg(&slopes[h]);
    const float fi = (float)i;

    const unsigned j0 = threadIdx.x * 4u;
    const float fj = (float)j0;

    float4 v;
    v.x = neg_slope * fabsf(fi - fj);
    v.y = neg_slope * fabsf(fi - (fj + 1.0f));
    v.z = neg_slope * fabsf(fi - (fj + 2.0f));
    v.w = neg_slope * fabsf(fi - (fj + 3.0f));

    float4* dst = reinterpret_cast<float4*>(out + (size_t)row * S + j0);
    *dst = v;
}

extern "C" void kernel_launch(void* const* d_in, const int* in_sizes, int n_in,
                              void* d_out, int out_size) {
    const float* slopes = (const float*)d_in[0];
    float* out = (float*)d_out;

    const unsigned grid = Z_TOTAL * S;   // 131072 blocks
    alibi_kernel<<<grid, THREADS>>>(slopes, out);
}

// round 8
// speedup vs baseline: 1.0035x; 1.0035x over previous
#include <cuda_runtime.h>
#include <cuda_bf16.h>

// ALiBi bias materialization:
//   out[z, i, j] = -slopes[z % 16] * |i - j|
//   z in [0, 64)  (h = z % 16), i, j in [0, 2048)
// Output: 64 * 2048 * 2048 fp32 = 1 GiB -> pure HBM-write-bound.
//
// FINAL: best-measured shape family (147.3us wall, ~7.0 TB/s, 86% DRAM
// duty = the write wall). 512 threads, 2 rows per block (same head ->
// uniform slope), one STG.128 per thread per row; grid 65536. Verified
// non-levers across R1-R7: store width (128/256b), .cs policy, block
// fatness, occupancy 48-90%, persistence (regressed 21%).

#define S        2048
#define NUM_H    16
#define Z_TOTAL  64
#define THREADS  512
#define ROWS_PER_BLOCK 2

__global__ __launch_bounds__(THREADS)
void alibi_kernel(const float* __restrict__ slopes, float* __restrict__ out) {
    const unsigned row0 = blockIdx.x * ROWS_PER_BLOCK;   // [0, 131072) step 2
    const unsigned h    = (row0 >> 11) & (NUM_H - 1);    // z % 16, block-uniform

    const float neg_slope = -__ldg(&slopes[h]);

    const unsigned j0 = threadIdx.x * 4u;
    const float fj = (float)j0;

    float* base = out + (size_t)row0 * S + j0;

#pragma unroll
    for (int r = 0; r < ROWS_PER_BLOCK; r++) {
        const float fi = (float)((row0 + r) & (S - 1));

        float4 v;
        v.x = neg_slope * fabsf(fi - fj);
        v.y = neg_slope * fabsf(fi - (fj + 1.0f));
        v.z = neg_slope * fabsf(fi - (fj + 2.0f));
        v.w = neg_slope * fabsf(fi - (fj + 3.0f));

        *reinterpret_cast<float4*>(base + (size_t)r * S) = v;
    }
}

extern "C" void kernel_launch(void* const* d_in, const int* in_sizes, int n_in,
                              void* d_out, int out_size) {
    const float* slopes = (const float*)d_in[0];
    float* out = (float*)d_out;

    const unsigned grid = (Z_TOTAL * S) / ROWS_PER_BLOCK;   // 65536
    alibi_kernel<<<grid, THREADS>>>(slopes, out);
}